// round 16
// baseline (speedup 1.0000x reference)
#include <cuda_runtime.h>
#include <cstdint>

// B=4096, D=1000, tiers: [0,50)x[475,1000), [475,525)x[950,1000), gt: n x [n,1000) * 2/D
#define D_DIM   1000
#define TSIZE   50
#define T0_S2   475
#define T1_S2   950
#define MAXREL  8
#define NTW     128
#define WPC     4                 // warps (= rows) per CTA
#define WSTRIDE 1280              // floats per warp slab (5120 B, 16B-aligned)

__device__ __forceinline__ void cp_async16(uint32_t smem_addr, const void* gptr) {
    asm volatile("cp.async.cg.shared.global [%0], [%1], 16;" :: "r"(smem_addr), "l"(gptr));
}
__device__ __forceinline__ void cp_commit() {
    asm volatile("cp.async.commit_group;" ::: "memory");
}
__device__ __forceinline__ void cp_wait_all() {
    asm volatile("cp.async.wait_group 0;" ::: "memory");
}

// compare-exchange: keep min if d, else max
#define CE(v, pv, d) (v) = (d) ? fminf((v), (pv)) : fmaxf((v), (pv))

// Sort 64 floats ascending across one warp; element ids: a=lane, b=lane+32.
__device__ __forceinline__ void bitonic64(float& a, float& b, int lane)
{
    #pragma unroll
    for (int k = 2; k <= 16; k <<= 1) {
        #pragma unroll
        for (int j = k >> 1; j > 0; j >>= 1) {
            const bool d = ((lane & k) == 0) == ((lane & j) == 0);
            float pa = __shfl_xor_sync(0xffffffffu, a, j);
            float pb = __shfl_xor_sync(0xffffffffu, b, j);
            CE(a, pa, d); CE(b, pb, d);
        }
    }
    #pragma unroll
    for (int j = 16; j > 0; j >>= 1) {         // k=32: a asc, b desc
        const bool d = ((lane & j) == 0);
        float pa = __shfl_xor_sync(0xffffffffu, a, j);
        float pb = __shfl_xor_sync(0xffffffffu, b, j);
        CE(a, pa, d); CE(b, pb, !d);
    }
    { float lo = fminf(a, b), hi = fmaxf(a, b); a = lo; b = hi; }   // k=64, j=32
    #pragma unroll
    for (int j = 16; j > 0; j >>= 1) {
        const bool d = ((lane & j) == 0);
        float pa = __shfl_xor_sync(0xffffffffu, a, j);
        float pb = __shfl_xor_sync(0xffffffffu, b, j);
        CE(a, pa, d); CE(b, pb, d);
    }
}

// t = 1-s (descending; +inf pads -> -1e30), store sorted array + prefix sums.
__device__ __forceinline__ void finish_tier(float a, float b, int lane,
                                            float* __restrict__ srt,
                                            float* __restrict__ pre)
{
    const float ta = 1.0f - a, tb = 1.0f - b;
    srt[lane]      = ta;
    srt[lane + 32] = tb;
    float xa = ta;
    #pragma unroll
    for (int d = 1; d < 32; d <<= 1) {
        float y = __shfl_up_sync(0xffffffffu, xa, d);
        if (lane >= d) xa += y;
    }
    const float tot = __shfl_sync(0xffffffffu, xa, 31);
    float xb = tb;
    #pragma unroll
    for (int d = 1; d < 32; d <<= 1) {
        float y = __shfl_up_sync(0xffffffffu, xb, d);
        if (lane >= d) xb += y;
    }
    xb += tot;
    pre[lane + 1]  = xa;
    pre[lane + 33] = xb;
    if (lane == 0) pre[0] = 0.0f;
}

// 6-level count query, top-3 levels in registers: k = #{srt_i > -v}; pre[k] + k*v
__device__ __forceinline__ float tree_query(float v,
                                            const float* __restrict__ s0,
                                            const float* __restrict__ p0,
                                            float r31, float r15, float r47,
                                            float r7, float r23, float r39, float r55)
{
    const float key = -v;
    const bool c1 = (r31 > key);
    int k = c1 ? 32 : 0;
    const float mB = c1 ? r47 : r15;
    const bool c2 = (mB > key);
    k += c2 ? 16 : 0;
    const float mC = c1 ? (c2 ? r55 : r39) : (c2 ? r23 : r7);
    k += (mC > key) ? 8 : 0;
    if (s0[k + 3] > key) k += 4;
    if (s0[k + 1] > key) k += 2;
    if (s0[k]     > key) k += 1;
    return p0[k] + (float)k * v;
}

// GT direct sum: 8 anchors in registers; invalid anchors / masked queries = -1e30 -> 0
#define GT8(wq) do {                      \
    AG0 += fmaxf(tg0 + (wq), 0.0f);       \
    AG1 += fmaxf(tg1 + (wq), 0.0f);       \
    AG2 += fmaxf(tg2 + (wq), 0.0f);       \
    AG3 += fmaxf(tg3 + (wq), 0.0f);       \
    AG0 += fmaxf(tg4 + (wq), 0.0f);       \
    AG1 += fmaxf(tg5 + (wq), 0.0f);       \
    AG2 += fmaxf(tg6 + (wq), 0.0f);       \
    AG3 += fmaxf(tg7 + (wq), 0.0f);       \
} while (0)

__global__ __launch_bounds__(NTW, 8)
void mtw_kernel(const float* __restrict__ scores,
                const int*   __restrict__ labels,
                float* __restrict__ out, float inv_B, int B)
{
    const int tid  = threadIdx.x;
    const int lane = tid & 31;
    const int w    = tid >> 5;

    // Zero the poisoned output. Block 0 is resident in wave 1 (grid is a single
    // wave); this lands within ~50 cycles of grid start while every accumulate
    // atomic is >= ~8000 cycles into its block. Replays are stream-serialized.
    if (blockIdx.x == 0 && tid == 0) atomicExch(out, 0.0f);

    __shared__ __align__(16) float pool[WPC * WSTRIDE];
    __shared__ float wsum[WPC];

    float* S  = pool + w * WSTRIDE;   // row [0..1000)
    float* s0 = S + D_DIM;            // tier0 sorted t [64]
    float* p0 = s0 + 64;              // tier0 prefix  [65]
    float* s1 = p0 + 65;              // tier1 sorted t [64]
    float* p1 = s1 + 64;              // tier1 prefix  [65]

    const int  row   = blockIdx.x * WPC + w;
    const bool valid = (row < B);

    float loss = 0.0f;
    if (valid) {
        const float* sr = scores + (size_t)row * D_DIM;

        // ---- async row load into this warp's slab (250 x 16B) ------------
        const uint32_t sbase = (uint32_t)__cvta_generic_to_shared(S);
        #pragma unroll
        for (int i = lane; i < D_DIM / 4; i += 32)
            cp_async16(sbase + i * 16, (const float4*)sr + i);
        cp_commit();

        // ---- GT anchors: n from labels; 8 t's broadcast into registers ---
        const int lab = (lane < MAXREL) ? labels[(size_t)row * D_DIM + lane] : -1;
        const unsigned mm = __ballot_sync(0xffffffffu, lab > -1);
        const int n = __popc(mm);
        const float gv = (lane < MAXREL) ? sr[lane] : 0.0f;
        float tg0, tg1, tg2, tg3, tg4, tg5, tg6, tg7;
        {
            float u;
            u = __shfl_sync(0xffffffffu, gv, 0); tg0 = (0 < n) ? (1.0f - u) : -1e30f;
            u = __shfl_sync(0xffffffffu, gv, 1); tg1 = (1 < n) ? (1.0f - u) : -1e30f;
            u = __shfl_sync(0xffffffffu, gv, 2); tg2 = (2 < n) ? (1.0f - u) : -1e30f;
            u = __shfl_sync(0xffffffffu, gv, 3); tg3 = (3 < n) ? (1.0f - u) : -1e30f;
            u = __shfl_sync(0xffffffffu, gv, 4); tg4 = (4 < n) ? (1.0f - u) : -1e30f;
            u = __shfl_sync(0xffffffffu, gv, 5); tg5 = (5 < n) ? (1.0f - u) : -1e30f;
            u = __shfl_sync(0xffffffffu, gv, 6); tg6 = (6 < n) ? (1.0f - u) : -1e30f;
            u = __shfl_sync(0xffffffffu, gv, 7); tg7 = (7 < n) ? (1.0f - u) : -1e30f;
        }

        // ---- both 50-anchor sorts + prefix sums (hides the cp.async) -----
        float a0 = sr[lane];
        float b0 = (lane < TSIZE - 32) ? sr[lane + 32] : 1e30f;
        float a1 = sr[T0_S2 + lane];
        float b1 = (lane < TSIZE - 32) ? sr[T0_S2 + lane + 32] : 1e30f;
        bitonic64(a0, b0, lane);
        bitonic64(a1, b1, lane);
        finish_tier(a0, b0, lane, s0, p0);
        finish_tier(a1, b1, lane, s1, p1);

        cp_wait_all();
        __syncwarp();

        float A0 = 0.0f, A1 = 0.0f;
        float AG0 = 0.0f, AG1 = 0.0f, AG2 = 0.0f, AG3 = 0.0f;

        // ---- peel idx = lane: the only place idx < n is possible ---------
        {
            const float v  = S[lane];
            const float wq = (lane >= n) ? v : -1e30f;
            GT8(wq);
        }
        // ---- region [32, 475): GT only -----------------------------------
        for (int idx = lane + 32; idx < T0_S2; idx += 32) {
            const float v = S[idx];
            GT8(v);
        }
        // ---- region [475, 1000): GT + tier0 (+ tier1 for idx >= 950) -----
        const float r31 = s0[31], r15 = s0[15], r47 = s0[47];
        const float r7 = s0[7], r23 = s0[23], r39 = s0[39], r55 = s0[55];
        for (int idx = T0_S2 + lane; idx < D_DIM; idx += 32) {
            const float v = S[idx];
            GT8(v);
            A0 += tree_query(v, s0, p0, r31, r15, r47, r7, r23, r39, r55);
            if (idx >= T1_S2) {
                const float key = -v;
                int k = 0;
                #pragma unroll
                for (int st = 32; st; st >>= 1)
                    if (s1[k + st - 1] > key) k += st;
                A1 += p1[k] + (float)k * v;
            }
        }

        loss = A0 * (1.0f / (TSIZE * 525.0f))
             + A1 * (1.0f / (TSIZE * (float)TSIZE))
             + ((AG0 + AG1) + (AG2 + AG3)) * (2.0f / (float)D_DIM);
    }

    // ---- epilogue: warp reduce, 4-way smem combine, one atomic per CTA ---
    #pragma unroll
    for (int off = 16; off > 0; off >>= 1)
        loss += __shfl_xor_sync(0xffffffffu, loss, off);
    if (lane == 0) wsum[w] = loss;
    __syncthreads();
    if (tid == 0)
        atomicAdd(out, ((wsum[0] + wsum[1]) + (wsum[2] + wsum[3])) * inv_B);
}

extern "C" void kernel_launch(void* const* d_in, const int* in_sizes, int n_in,
                              void* d_out, int out_size)
{
    const float* scores = (const float*)d_in[0];
    const int*   labels = (const int*)d_in[1];
    float*       out    = (float*)d_out;

    const int B    = in_sizes[0] / D_DIM;
    const int grid = (B + WPC - 1) / WPC;

    mtw_kernel<<<grid, NTW>>>(scores, labels, out, 1.0f / (float)B, B);
}

// round 17
// speedup vs baseline: 1.1314x; 1.1314x over previous
#include <cuda_runtime.h>
#include <cstdint>

// B=4096, D=1000, tiers: [0,50)x[475,1000), [475,525)x[950,1000), gt: n x [n,1000) * 2/D
#define D_DIM   1000
#define TSIZE   50
#define T0_S2   475
#define T1_S1   475
#define T1_S2   950
#define MAXREL  8
#define NT      256

__device__ __forceinline__ void cp_async16(uint32_t smem_addr, const void* gptr) {
    asm volatile("cp.async.cg.shared.global [%0], [%1], 16;" :: "r"(smem_addr), "l"(gptr));
}
__device__ __forceinline__ void cp_commit() {
    asm volatile("cp.async.commit_group;" ::: "memory");
}
__device__ __forceinline__ void cp_wait_all() {
    asm volatile("cp.async.wait_group 0;" ::: "memory");
}

// compare-exchange: keep min if d, else max
#define CE(v, pv, d) (v) = (d) ? fminf((v), (pv)) : fmaxf((v), (pv))

// Sort 64 floats ascending across one warp; element ids: a=lane, b=lane+32.
__device__ __forceinline__ void bitonic64(float& a, float& b, int lane)
{
    #pragma unroll
    for (int k = 2; k <= 16; k <<= 1) {
        #pragma unroll
        for (int j = k >> 1; j > 0; j >>= 1) {
            const bool d = ((lane & k) == 0) == ((lane & j) == 0);
            float pa = __shfl_xor_sync(0xffffffffu, a, j);
            float pb = __shfl_xor_sync(0xffffffffu, b, j);
            CE(a, pa, d); CE(b, pb, d);
        }
    }
    #pragma unroll
    for (int j = 16; j > 0; j >>= 1) {         // k=32: a asc, b desc
        const bool d = ((lane & j) == 0);
        float pa = __shfl_xor_sync(0xffffffffu, a, j);
        float pb = __shfl_xor_sync(0xffffffffu, b, j);
        CE(a, pa, d); CE(b, pb, !d);
    }
    { float lo = fminf(a, b), hi = fmaxf(a, b); a = lo; b = hi; }   // k=64, j=32
    #pragma unroll
    for (int j = 16; j > 0; j >>= 1) {
        const bool d = ((lane & j) == 0);
        float pa = __shfl_xor_sync(0xffffffffu, a, j);
        float pb = __shfl_xor_sync(0xffffffffu, b, j);
        CE(a, pa, d); CE(b, pb, d);
    }
}

// t = 1-s (descending; +inf pads -> -1e30), store sorted array + prefix sums.
__device__ __forceinline__ void finish_tier(float a, float b, int lane,
                                            float* __restrict__ srt,
                                            float* __restrict__ pre)
{
    const float ta = 1.0f - a, tb = 1.0f - b;
    srt[lane]      = ta;
    srt[lane + 32] = tb;
    float xa = ta;
    #pragma unroll
    for (int d = 1; d < 32; d <<= 1) {
        float y = __shfl_up_sync(0xffffffffu, xa, d);
        if (lane >= d) xa += y;
    }
    const float tot = __shfl_sync(0xffffffffu, xa, 31);
    float xb = tb;
    #pragma unroll
    for (int d = 1; d < 32; d <<= 1) {
        float y = __shfl_up_sync(0xffffffffu, xb, d);
        if (lane >= d) xb += y;
    }
    xb += tot;
    pre[lane + 1]  = xa;
    pre[lane + 33] = xb;
    if (lane == 0) pre[0] = 0.0f;
}

// 6-level count query, top-3 levels in registers: k = #{srt_i > -v}; pre[k] + k*v
__device__ __forceinline__ float tree_query(float v,
                                            const float* __restrict__ s0,
                                            const float* __restrict__ p0,
                                            float r31, float r15, float r47,
                                            float r7, float r23, float r39, float r55)
{
    const float key = -v;
    const bool c1 = (r31 > key);
    int k = c1 ? 32 : 0;
    const float mB = c1 ? r47 : r15;
    const bool c2 = (mB > key);
    k += c2 ? 16 : 0;
    const float mC = c1 ? (c2 ? r55 : r39) : (c2 ? r23 : r7);
    k += (mC > key) ? 8 : 0;
    if (s0[k + 3] > key) k += 4;
    if (s0[k + 1] > key) k += 2;
    if (s0[k]     > key) k += 1;
    return p0[k] + (float)k * v;
}

// GT direct hinge sum of one query vs 8 register anchors (invalid = -1e30 -> 0)
#define GT8(wq) do {                      \
    AG0 += fmaxf(tg0 + (wq), 0.0f);       \
    AG1 += fmaxf(tg1 + (wq), 0.0f);       \
    AG2 += fmaxf(tg2 + (wq), 0.0f);       \
    AG3 += fmaxf(tg3 + (wq), 0.0f);       \
    AG0 += fmaxf(tg4 + (wq), 0.0f);       \
    AG1 += fmaxf(tg5 + (wq), 0.0f);       \
    AG2 += fmaxf(tg6 + (wq), 0.0f);       \
    AG3 += fmaxf(tg7 + (wq), 0.0f);       \
} while (0)

__global__ __launch_bounds__(NT, 7)
void mt3_kernel(const float* __restrict__ scores,
                const int*   __restrict__ labels,
                float* __restrict__ out, float inv_B, int B)
{
    const int tid  = threadIdx.x;
    const int lane = tid & 31;
    const int wid  = tid >> 5;
    const int tl   = tid & 127;           // thread-in-half
    const int rs   = tid >> 7;            // 0 = row A, 1 = row B
    const int wloc = wid & 3;             // task within the half

    // Zero the poisoned output. Block 0 is resident in wave 1; this lands within
    // ~50 cycles of grid start; every accumulate atomic is >= ~2000 cycles into
    // its block. Graph replays are stream-serialized.
    if (blockIdx.x == 0 && tid == 0) atomicExch(out, 0.0f);

    __shared__ __align__(16) float s[2][D_DIM];  // two rows
    __shared__ float srt[2][2][64];              // [row][tier] sorted-desc t, -1e30 pad
    __shared__ float pre[2][2][65];              // [row][tier] prefix sums
    __shared__ float wsum[NT / 32];

    const int  rA     = blockIdx.x * 2;
    const bool bValid = (rA + 1 < B);
    const int  myRow  = (rs && bValid) ? rA + 1 : rA;   // clamp: safe loads
    const float* src  = scores + (size_t)myRow * D_DIM;

    // ---- everyone async-loads its slice of its half's row ---------------
    {
        const uint32_t sb = (uint32_t)__cvta_generic_to_shared(s[rs]);
        cp_async16(sb + tl * 16, (const float4*)src + tl);
        if (tl < 250 - 128)
            cp_async16(sb + (tl + 128) * 16, (const float4*)src + tl + 128);
        cp_commit();
    }

    float AG0 = 0.f, AG1 = 0.f, AG2 = 0.f, AG3 = 0.f;

    if (wloc < 2) {
        // ---- sort warps: anchors straight from gmem (no dependencies) ----
        const int base = wloc ? T1_S1 : 0;
        float a = __ldg(src + base + lane);
        float b = (lane < TSIZE - 32) ? __ldg(src + base + lane + 32) : 1e30f;
        bitonic64(a, b, lane);
        finish_tier(a, b, lane, srt[rs][wloc], pre[rs][wloc]);
    } else {
        // ---- GT warps: whole row's GT from gmem, overlaps the sort chain -
        const int g = lane + ((wloc - 2) << 5);           // 0..63 within half
        const int lab = (lane < MAXREL)
                      ? labels[(size_t)myRow * D_DIM + lane] : -1;
        const unsigned mm = __ballot_sync(0xffffffffu, lab > -1);
        const int n = __popc(mm);
        const float gv = (lane < MAXREL) ? __ldg(src + lane) : 0.0f;
        float tg0, tg1, tg2, tg3, tg4, tg5, tg6, tg7;
        {
            float u;
            u = __shfl_sync(0xffffffffu, gv, 0); tg0 = (0 < n) ? (1.0f - u) : -1e30f;
            u = __shfl_sync(0xffffffffu, gv, 1); tg1 = (1 < n) ? (1.0f - u) : -1e30f;
            u = __shfl_sync(0xffffffffu, gv, 2); tg2 = (2 < n) ? (1.0f - u) : -1e30f;
            u = __shfl_sync(0xffffffffu, gv, 3); tg3 = (3 < n) ? (1.0f - u) : -1e30f;
            u = __shfl_sync(0xffffffffu, gv, 4); tg4 = (4 < n) ? (1.0f - u) : -1e30f;
            u = __shfl_sync(0xffffffffu, gv, 5); tg5 = (5 < n) ? (1.0f - u) : -1e30f;
            u = __shfl_sync(0xffffffffu, gv, 6); tg6 = (6 < n) ? (1.0f - u) : -1e30f;
            u = __shfl_sync(0xffffffffu, gv, 7); tg7 = (7 < n) ? (1.0f - u) : -1e30f;
        }
        const float4* s4 = (const float4*)src;
        #pragma unroll
        for (int blk = g; blk < 250; blk += 64) {
            float4 v = __ldg(s4 + blk);
            if (blk < 2) {                    // only idx 0..7 can be < n
                const int b4 = blk * 4;
                v.x = (b4 + 0 >= n) ? v.x : -1e30f;
                v.y = (b4 + 1 >= n) ? v.y : -1e30f;
                v.z = (b4 + 2 >= n) ? v.z : -1e30f;
                v.w = (b4 + 3 >= n) ? v.w : -1e30f;
            }
            GT8(v.x); GT8(v.y); GT8(v.z); GT8(v.w);
        }
    }

    cp_wait_all();
    __syncthreads();

    // ================= tier queries: half-block per row ===================
    const float* sR = s[rs];
    float A0 = 0.0f, A1 = 0.0f;

    // ---- tier0: 525 = 128*4 + 13 queries per row -------------------------
    {
        const float* s0 = srt[rs][0];
        const float* p0 = pre[rs][0];
        const float r31 = s0[31], r15 = s0[15], r47 = s0[47];
        const float r7 = s0[7], r23 = s0[23], r39 = s0[39], r55 = s0[55];
        #pragma unroll
        for (int q = 0; q < 4; q++)
            A0 += tree_query(sR[T0_S2 + tl + q * 128], s0, p0,
                             r31, r15, r47, r7, r23, r39, r55);
        if (tl < 525 - 512)
            A0 += tree_query(sR[T0_S2 + 512 + tl], s0, p0,
                             r31, r15, r47, r7, r23, r39, r55);
    }

    // ---- tier1: 50 queries on tl in [64,114) per row ---------------------
    if (tl >= 64 && tl < 64 + TSIZE) {
        const float v   = sR[T1_S2 + (tl - 64)];
        const float key = -v;
        int k = 0;
        #pragma unroll
        for (int st = 32; st; st >>= 1)
            if (srt[rs][1][k + st - 1] > key) k += st;
        A1 = pre[rs][1][k] + (float)k * v;
    }

    const float fv = (rs == 0 || bValid) ? 1.0f : 0.0f;
    float loss = (A0 * (1.0f / (TSIZE * 525.0f))
                + A1 * (1.0f / (TSIZE * (float)TSIZE))
                + ((AG0 + AG1) + (AG2 + AG3)) * (2.0f / (float)D_DIM)) * fv;

    // ---- block reduce + single atomic (covers both rows) -----------------
    #pragma unroll
    for (int off = 16; off > 0; off >>= 1)
        loss += __shfl_xor_sync(0xffffffffu, loss, off);
    if (lane == 0) wsum[wid] = loss;
    __syncthreads();
    if (tid == 0) {
        float t = 0.0f;
        #pragma unroll
        for (int w2 = 0; w2 < NT / 32; w2++) t += wsum[w2];
        atomicAdd(out, t * inv_B);
    }
}

extern "C" void kernel_launch(void* const* d_in, const int* in_sizes, int n_in,
                              void* d_out, int out_size)
{
    const float* scores = (const float*)d_in[0];
    const int*   labels = (const int*)d_in[1];
    float*       out    = (float*)d_out;

    const int B    = in_sizes[0] / D_DIM;
    const int grid = (B + 1) / 2;

    mt3_kernel<<<grid, NT>>>(scores, labels, out, 1.0f / (float)B, B);
}